// round 12
// baseline (speedup 1.0000x reference)
#include <cuda_runtime.h>
#include <cuda_bf16.h>
#include <cstdint>

#define B   256
#define T   1024
#define H   128
#define I   19
#define BT  (B*T)            // 262144
#define NEL (BT*H)           // 33554432

// Scratch (device globals: allocation-free per harness rules)
__device__ float g_pre[NEL];   // pre-activations (layer0, then layer1)
__device__ float g_h1[NEL];    // layer-0 hidden outputs

typedef unsigned long long u64;

__device__ __forceinline__ u64 fma2(u64 a, u64 b, u64 c) {
    u64 d;
    asm("fma.rn.f32x2 %0, %1, %2, %3;" : "=l"(d) : "l"(a), "l"(b), "l"(c));
    return d;
}
__device__ __forceinline__ u64 add2(u64 a, u64 b) {
    u64 d;
    asm("add.rn.f32x2 %0, %1, %2;" : "=l"(d) : "l"(a), "l"(b));
    return d;
}
__device__ __forceinline__ u64 dup2(float w) {
    u64 d;
    asm("mov.b64 %0, {%1, %1};" : "=l"(d) : "f"(w));
    return d;
}
__device__ __forceinline__ float red2(u64 a) {
    float x, y;
    asm("mov.b64 {%0, %1}, %2;" : "=f"(x), "=f"(y) : "l"(a));
    return x + y;
}
__device__ __forceinline__ void unpack2(u64 a, float& x, float& y) {
    asm("mov.b64 {%0, %1}, %2;" : "=f"(x), "=f"(y) : "l"(a));
}
__device__ __forceinline__ float fast_tanh(float x) {
    float r;
    asm("tanh.approx.f32 %0, %1;" : "=f"(r) : "f"(x));
    return r;
}
__device__ __forceinline__ void cp16(uint32_t daddr, const void* gptr) {
    asm volatile("cp.async.ca.shared.global [%0], [%1], 16;\n"
                 :: "r"(daddr), "l"(gptr));
}

// ---------------------------------------------------------------------------
// Kernel 1: pre0 (proven in round 5)
// ---------------------------------------------------------------------------
#define P0_ROWS 64
#define P0_F4   ((P0_ROWS * I) / 4)   // 304

__global__ void __launch_bounds__(128)
pre0_kernel(const float* __restrict__ x,
            const float* __restrict__ W,
            const float* __restrict__ bi,
            const float* __restrict__ bh) {
    __shared__ __align__(16) float xs[P0_ROWS * I];
    const int j = threadIdx.x;

    float w[I];
#pragma unroll
    for (int f = 0; f < I; f++) w[f] = __ldg(W + j * I + f);
    const float bias = __ldg(bi + j) + __ldg(bh + j);

    const int rbeg = blockIdx.x * P0_ROWS;
    const float4* src = reinterpret_cast<const float4*>(x + (size_t)rbeg * I);
    float4* dst = reinterpret_cast<float4*>(xs);
    dst[j] = src[j];
    dst[j + 128] = src[j + 128];
    if (j < P0_F4 - 256) dst[j + 256] = src[j + 256];
    __syncthreads();

    float* outp = g_pre + (size_t)rbeg * H + j;
#pragma unroll 4
    for (int r = 0; r < P0_ROWS; r += 4) {
        float a0 = bias, a1 = bias, a2 = bias, a3 = bias;
#pragma unroll
        for (int f = 0; f < I; f++) {
            a0 = fmaf(xs[(r + 0) * I + f], w[f], a0);
            a1 = fmaf(xs[(r + 1) * I + f], w[f], a1);
            a2 = fmaf(xs[(r + 2) * I + f], w[f], a2);
            a3 = fmaf(xs[(r + 3) * I + f], w[f], a3);
        }
        outp[(r + 0) * H] = a0;
        outp[(r + 1) * H] = a1;
        outp[(r + 2) * H] = a2;
        outp[(r + 3) * H] = a3;
    }
}

// ---------------------------------------------------------------------------
// Kernel 2: pair-packed split-K recurrent scan (fixed combine).
// 256 threads/CTA, grid = B/2: CTA handles batch rows r0 = 2*blk, r1 = 2*blk+1.
// Lane pair (2m, 2m+1) of warp w owns unit j = 16w + m; even lane covers
// k in [0,64), odd lane k in [64,128). Shared h is stored as PAIRS
// hpair[k] = (h_r0[k], h_r1[k]); weight duplicated into both f32x2 lanes, so
// ONE fma2 advances both batch rows: 64 fma2/thread/step.
// Combine: lane keeps its OWN row's partial and sends the PARTNER-ROW
// partial via shfl.xor(1).
// ---------------------------------------------------------------------------
#define RGN1 132   // float offset of k-half-1 region (128 + 4 skew)
#define BUFSZ 264

__global__ void __launch_bounds__(256, 1)
scan_kernel(int layer, const float* __restrict__ Whh, float* __restrict__ dout) {
    __shared__ __align__(16) float bufA[BUFSZ], bufB[BUFSZ];
    const int tid  = threadIdx.x;
    const int w    = tid >> 5;
    const int l    = tid & 31;
    const int m    = l >> 1;
    const int half = l & 1;
    const int j    = (w << 4) + m;

    const float* __restrict__ pre = g_pre;
    float* __restrict__ out = (layer == 0) ? g_h1 : dout;

    // Duplicated-pair weights for this thread's 64 k values.
    u64 wd[64];
    {
        const float* wr = Whh + j * H + (half << 6);
#pragma unroll
        for (int q = 0; q < 64; q++) wd[q] = dup2(__ldg(wr + q));
    }

    const float* rdA = bufA + (half ? RGN1 : 0);
    const float* rdB = bufB + (half ? RGN1 : 0);
    const int wslot = ((j < 64) ? (2 * j) : (RGN1 + 2 * (j - 64))) + half;

    // Post-combine, this lane finishes row `half`.
    const int myrow = 2 * blockIdx.x + half;
    const size_t base = (size_t)myrow * (T * H) + j;

    bufA[wslot] = 0.0f;                 // h(-1) = 0
    float pA = __ldg(pre + base);           // pre for even steps
    float pB = __ldg(pre + base + H);       // pre for odd steps
    __syncthreads();

#pragma unroll 1
    for (int t = 0; t < T; t += 2) {
        // ---- even step: read bufA, write bufB ----
        {
            const ulonglong2* hp = reinterpret_cast<const ulonglong2*>(rdA);
            u64 a0 = 0, a1 = 0, a2 = 0, a3 = 0;
#pragma unroll
            for (int i = 0; i < 16; i++) {
                ulonglong2 q0 = hp[2 * i], q1 = hp[2 * i + 1];
                a0 = fma2(wd[4 * i + 0], q0.x, a0);
                a1 = fma2(wd[4 * i + 1], q0.y, a1);
                a2 = fma2(wd[4 * i + 2], q1.x, a2);
                a3 = fma2(wd[4 * i + 3], q1.y, a3);
            }
            float s0, s1;
            unpack2(add2(add2(a0, a2), add2(a1, a3)), s0, s1);
            float keep = half ? s1 : s0;    // my row, my k-half
            float send = half ? s0 : s1;    // partner's row, my k-half
            float d = keep + __shfl_xor_sync(0xffffffffu, send, 1);
            float h = fast_tanh(pA + d);
            bufB[wslot] = h;
            out[base + (size_t)t * H] = h;
            int tn = (t + 2 < T) ? (t + 2) : (T - 1);
            pA = __ldg(pre + base + (size_t)tn * H);
            __syncthreads();
        }
        // ---- odd step: read bufB, write bufA ----
        {
            const ulonglong2* hp = reinterpret_cast<const ulonglong2*>(rdB);
            u64 a0 = 0, a1 = 0, a2 = 0, a3 = 0;
#pragma unroll
            for (int i = 0; i < 16; i++) {
                ulonglong2 q0 = hp[2 * i], q1 = hp[2 * i + 1];
                a0 = fma2(wd[4 * i + 0], q0.x, a0);
                a1 = fma2(wd[4 * i + 1], q0.y, a1);
                a2 = fma2(wd[4 * i + 2], q1.x, a2);
                a3 = fma2(wd[4 * i + 3], q1.y, a3);
            }
            float s0, s1;
            unpack2(add2(add2(a0, a2), add2(a1, a3)), s0, s1);
            float keep = half ? s1 : s0;
            float send = half ? s0 : s1;
            float d = keep + __shfl_xor_sync(0xffffffffu, send, 1);
            float h = fast_tanh(pB + d);
            bufA[wslot] = h;
            out[base + (size_t)(t + 1) * H] = h;
            int tn = (t + 3 < T) ? (t + 3) : (T - 1);
            pB = __ldg(pre + base + (size_t)tn * H);
            __syncthreads();
        }
    }
}

// ---------------------------------------------------------------------------
// Kernel 3: layer-1 input projection, 4-stage cp.async pipeline (round 5).
// ---------------------------------------------------------------------------
#define PROJ_BLOCKS 512
#define PROJ_ROWS   (BT / PROJ_BLOCKS)   // 512
#define PTILE       8
#define NTILES      (PROJ_ROWS / PTILE)  // 64
#define NSTAGE      4
#define STAGE_BYTES (PTILE * H * 4)      // 4096

__global__ void __launch_bounds__(128, 2)
proj_kernel(const float* __restrict__ W,
            const float* __restrict__ bi,
            const float* __restrict__ bh) {
    __shared__ __align__(16) float sh[NSTAGE][PTILE * H];
    const int j = threadIdx.x;
    const uint32_t shbase = (uint32_t)__cvta_generic_to_shared(sh);

    u64 wp[64];
    const u64* wrow = reinterpret_cast<const u64*>(W + j * H);
#pragma unroll
    for (int i = 0; i < 64; i++) wp[i] = __ldg(wrow + i);

    const float bias = __ldg(bi + j) + __ldg(bh + j);
    const int rbeg = blockIdx.x * PROJ_ROWS;

#pragma unroll
    for (int s = 0; s < 3; s++) {
        const float4* src = reinterpret_cast<const float4*>(
            g_h1 + (size_t)(rbeg + s * PTILE) * H);
        uint32_t d = shbase + s * STAGE_BYTES + j * 16;
        cp16(d, src + j);
        cp16(d + 2048, src + j + 128);
        asm volatile("cp.async.commit_group;\n");
    }

#pragma unroll 1
    for (int ti = 0; ti < NTILES; ti++) {
        asm volatile("cp.async.wait_group 2;\n");
        __syncthreads();

        if (ti + 3 < NTILES) {
            int s = (ti + 3) & (NSTAGE - 1);
            const float4* src = reinterpret_cast<const float4*>(
                g_h1 + (size_t)(rbeg + (ti + 3) * PTILE) * H);
            uint32_t d = shbase + s * STAGE_BYTES + j * 16;
            cp16(d, src + j);
            cp16(d + 2048, src + j + 128);
            asm volatile("cp.async.commit_group;\n");
        }

        const float* stage = sh[ti & (NSTAGE - 1)];
        float* outp = g_pre + (size_t)(rbeg + ti * PTILE) * H + j;
#pragma unroll
        for (int i = 0; i < PTILE; i++) {
            const ulonglong2* hp = reinterpret_cast<const ulonglong2*>(stage + i * H);
            u64 a0 = 0, a1 = 0, a2 = 0, a3 = 0;
#pragma unroll
            for (int q = 0; q < 16; q++) {
                ulonglong2 x0 = hp[2 * q], x1 = hp[2 * q + 1];
                a0 = fma2(wp[4 * q + 0], x0.x, a0);
                a1 = fma2(wp[4 * q + 1], x0.y, a1);
                a2 = fma2(wp[4 * q + 2], x1.x, a2);
                a3 = fma2(wp[4 * q + 3], x1.y, a3);
            }
            outp[i * H] = bias + red2(add2(add2(a0, a2), add2(a1, a3)));
        }
        __syncthreads();
    }
}

// ---------------------------------------------------------------------------
extern "C" void kernel_launch(void* const* d_in, const int* in_sizes, int n_in,
                              void* d_out, int out_size) {
    const float* x     = (const float*)d_in[0];
    const float* W_ih0 = (const float*)d_in[1];
    const float* W_hh0 = (const float*)d_in[2];
    const float* b_ih0 = (const float*)d_in[3];
    const float* b_hh0 = (const float*)d_in[4];
    const float* W_ih1 = (const float*)d_in[5];
    const float* W_hh1 = (const float*)d_in[6];
    const float* b_ih1 = (const float*)d_in[7];
    const float* b_hh1 = (const float*)d_in[8];
    float* out = (float*)d_out;

    // Layer 0 input projection -> g_pre
    pre0_kernel<<<BT / P0_ROWS, 128>>>(x, W_ih0, b_ih0, b_hh0);
    // Layer 0 scan (pair-packed, 2 rows/CTA): g_pre -> g_h1
    scan_kernel<<<B / 2, 256>>>(0, W_hh0, out);
    // Layer 1 input projection: g_h1 -> g_pre
    proj_kernel<<<PROJ_BLOCKS, 128>>>(W_ih1, b_ih1, b_hh1);
    // Layer 1 scan (pair-packed): g_pre -> out
    scan_kernel<<<B / 2, 256>>>(1, W_hh1, out);
}

// round 13
// speedup vs baseline: 1.6861x; 1.6861x over previous
#include <cuda_runtime.h>
#include <cuda_bf16.h>
#include <cstdint>

#define B   256
#define T   1024
#define H   128
#define I   19
#define BT  (B*T)            // 262144
#define NEL (BT*H)           // 33554432

// Scratch (device globals: allocation-free per harness rules)
__device__ float g_pre[NEL];   // pre-activations (layer0, then layer1)
__device__ float g_h1[NEL];    // layer-0 hidden outputs

typedef unsigned long long u64;

__device__ __forceinline__ u64 fma2(u64 a, u64 b, u64 c) {
    u64 d;
    asm("fma.rn.f32x2 %0, %1, %2, %3;" : "=l"(d) : "l"(a), "l"(b), "l"(c));
    return d;
}
__device__ __forceinline__ u64 add2(u64 a, u64 b) {
    u64 d;
    asm("add.rn.f32x2 %0, %1, %2;" : "=l"(d) : "l"(a), "l"(b));
    return d;
}
__device__ __forceinline__ float red2(u64 a) {
    float x, y;
    asm("mov.b64 {%0, %1}, %2;" : "=f"(x), "=f"(y) : "l"(a));
    return x + y;
}
__device__ __forceinline__ float fast_tanh(float x) {
    float r;
    asm("tanh.approx.f32 %0, %1;" : "=f"(r) : "f"(x));
    return r;
}
__device__ __forceinline__ void cp16(uint32_t daddr, const void* gptr) {
    asm volatile("cp.async.ca.shared.global [%0], [%1], 16;\n"
                 :: "r"(daddr), "l"(gptr));
}

// ---------------------------------------------------------------------------
// Kernel 1: pre0 (proven in round 5)
// ---------------------------------------------------------------------------
#define P0_ROWS 64
#define P0_F4   ((P0_ROWS * I) / 4)   // 304

__global__ void __launch_bounds__(128)
pre0_kernel(const float* __restrict__ x,
            const float* __restrict__ W,
            const float* __restrict__ bi,
            const float* __restrict__ bh) {
    __shared__ __align__(16) float xs[P0_ROWS * I];
    const int j = threadIdx.x;

    float w[I];
#pragma unroll
    for (int f = 0; f < I; f++) w[f] = __ldg(W + j * I + f);
    const float bias = __ldg(bi + j) + __ldg(bh + j);

    const int rbeg = blockIdx.x * P0_ROWS;
    const float4* src = reinterpret_cast<const float4*>(x + (size_t)rbeg * I);
    float4* dst = reinterpret_cast<float4*>(xs);
    dst[j] = src[j];
    dst[j + 128] = src[j + 128];
    if (j < P0_F4 - 256) dst[j + 256] = src[j + 256];
    __syncthreads();

    float* outp = g_pre + (size_t)rbeg * H + j;
#pragma unroll 4
    for (int r = 0; r < P0_ROWS; r += 4) {
        float a0 = bias, a1 = bias, a2 = bias, a3 = bias;
#pragma unroll
        for (int f = 0; f < I; f++) {
            a0 = fmaf(xs[(r + 0) * I + f], w[f], a0);
            a1 = fmaf(xs[(r + 1) * I + f], w[f], a1);
            a2 = fmaf(xs[(r + 2) * I + f], w[f], a2);
            a3 = fmaf(xs[(r + 3) * I + f], w[f], a3);
        }
        outp[(r + 0) * H] = a0;
        outp[(r + 1) * H] = a1;
        outp[(r + 2) * H] = a2;
        outp[(r + 3) * H] = a3;
    }
}

// ---------------------------------------------------------------------------
// Kernel 2: recurrent scan — EXACT round-5 proven structure (454us).
// One CTA (128 thr) per batch row; thread j owns unit j, W_hh row j in 64
// packed f32x2 registers, h double-buffered in shared, manual 2x unroll
// with static prefetch registers. One __syncthreads per step.
// ---------------------------------------------------------------------------
__global__ void __launch_bounds__(128, 2)
scan_kernel(int layer, const float* __restrict__ Whh, float* __restrict__ dout) {
    __shared__ __align__(16) float hAb[H], hBb[H];
    const int j = threadIdx.x;
    const int b = blockIdx.x;
    const float* __restrict__ pre = g_pre;
    float* __restrict__ out = (layer == 0) ? g_h1 : dout;

    u64 wp[64];
    const u64* wrow = reinterpret_cast<const u64*>(Whh + j * H);
#pragma unroll
    for (int i = 0; i < 64; i++) wp[i] = __ldg(wrow + i);

    hAb[j] = 0.0f;
    const int base = b * (T * H) + j;
    float pA = __ldg(pre + base);
    float pB = __ldg(pre + base + H);
    __syncthreads();

#pragma unroll 1
    for (int t = 0; t < T; t += 2) {
        {
            const ulonglong2* hp = reinterpret_cast<const ulonglong2*>(hAb);
            u64 a0 = 0, a1 = 0, a2 = 0, a3 = 0;
#pragma unroll
            for (int i = 0; i < 16; i++) {
                ulonglong2 q0 = hp[2 * i], q1 = hp[2 * i + 1];
                a0 = fma2(wp[4 * i + 0], q0.x, a0);
                a1 = fma2(wp[4 * i + 1], q0.y, a1);
                a2 = fma2(wp[4 * i + 2], q1.x, a2);
                a3 = fma2(wp[4 * i + 3], q1.y, a3);
            }
            float h = fast_tanh(pA + red2(add2(add2(a0, a2), add2(a1, a3))));
            hBb[j] = h;
            out[base + t * H] = h;
            int tn = (t + 2 < T) ? (t + 2) : (T - 1);
            pA = __ldg(pre + base + tn * H);
            __syncthreads();
        }
        {
            const ulonglong2* hp = reinterpret_cast<const ulonglong2*>(hBb);
            u64 a0 = 0, a1 = 0, a2 = 0, a3 = 0;
#pragma unroll
            for (int i = 0; i < 16; i++) {
                ulonglong2 q0 = hp[2 * i], q1 = hp[2 * i + 1];
                a0 = fma2(wp[4 * i + 0], q0.x, a0);
                a1 = fma2(wp[4 * i + 1], q0.y, a1);
                a2 = fma2(wp[4 * i + 2], q1.x, a2);
                a3 = fma2(wp[4 * i + 3], q1.y, a3);
            }
            float h = fast_tanh(pB + red2(add2(add2(a0, a2), add2(a1, a3))));
            hAb[j] = h;
            out[base + (t + 1) * H] = h;
            int tn = (t + 3 < T) ? (t + 3) : (T - 1);
            pB = __ldg(pre + base + tn * H);
            __syncthreads();
        }
    }
}

// ---------------------------------------------------------------------------
// Kernel 3: layer-1 input projection, 4-stage cp.async pipeline.
// CHANGE vs round 5: 2048 CTAs (128 rows each) instead of 512 — latency is
// now hidden by CTA-level parallelism (7 waves at occ 2) on top of the
// 4-stage pipeline, attacking the ~3x gap between measured (~260us) and
// the ~90us issue/BW floor.
// ---------------------------------------------------------------------------
#define PROJ_BLOCKS 2048
#define PROJ_ROWS   (BT / PROJ_BLOCKS)   // 128 rows per block
#define PTILE       8
#define NTILES      (PROJ_ROWS / PTILE)  // 16
#define NSTAGE      4
#define STAGE_BYTES (PTILE * H * 4)      // 4096

__global__ void __launch_bounds__(128, 2)
proj_kernel(const float* __restrict__ W,
            const float* __restrict__ bi,
            const float* __restrict__ bh) {
    __shared__ __align__(16) float sh[NSTAGE][PTILE * H];
    const int j = threadIdx.x;
    const uint32_t shbase = (uint32_t)__cvta_generic_to_shared(sh);

    u64 wp[64];
    const u64* wrow = reinterpret_cast<const u64*>(W + j * H);
#pragma unroll
    for (int i = 0; i < 64; i++) wp[i] = __ldg(wrow + i);

    const float bias = __ldg(bi + j) + __ldg(bh + j);
    const int rbeg = blockIdx.x * PROJ_ROWS;

#pragma unroll
    for (int s = 0; s < 3; s++) {
        const float4* src = reinterpret_cast<const float4*>(
            g_h1 + (size_t)(rbeg + s * PTILE) * H);
        uint32_t d = shbase + s * STAGE_BYTES + j * 16;
        cp16(d, src + j);
        cp16(d + 2048, src + j + 128);
        asm volatile("cp.async.commit_group;\n");
    }

#pragma unroll 1
    for (int ti = 0; ti < NTILES; ti++) {
        asm volatile("cp.async.wait_group 2;\n");
        __syncthreads();

        if (ti + 3 < NTILES) {
            int s = (ti + 3) & (NSTAGE - 1);
            const float4* src = reinterpret_cast<const float4*>(
                g_h1 + (size_t)(rbeg + (ti + 3) * PTILE) * H);
            uint32_t d = shbase + s * STAGE_BYTES + j * 16;
            cp16(d, src + j);
            cp16(d + 2048, src + j + 128);
            asm volatile("cp.async.commit_group;\n");
        }

        const float* stage = sh[ti & (NSTAGE - 1)];
        float* outp = g_pre + (size_t)(rbeg + ti * PTILE) * H + j;
#pragma unroll
        for (int i = 0; i < PTILE; i++) {
            const ulonglong2* hp = reinterpret_cast<const ulonglong2*>(stage + i * H);
            u64 a0 = 0, a1 = 0, a2 = 0, a3 = 0;
#pragma unroll
            for (int q = 0; q < 16; q++) {
                ulonglong2 x0 = hp[2 * q], x1 = hp[2 * q + 1];
                a0 = fma2(wp[4 * q + 0], x0.x, a0);
                a1 = fma2(wp[4 * q + 1], x0.y, a1);
                a2 = fma2(wp[4 * q + 2], x1.x, a2);
                a3 = fma2(wp[4 * q + 3], x1.y, a3);
            }
            outp[i * H] = bias + red2(add2(add2(a0, a2), add2(a1, a3)));
        }
        __syncthreads();
    }
}

// ---------------------------------------------------------------------------
extern "C" void kernel_launch(void* const* d_in, const int* in_sizes, int n_in,
                              void* d_out, int out_size) {
    const float* x     = (const float*)d_in[0];
    const float* W_ih0 = (const float*)d_in[1];
    const float* W_hh0 = (const float*)d_in[2];
    const float* b_ih0 = (const float*)d_in[3];
    const float* b_hh0 = (const float*)d_in[4];
    const float* W_ih1 = (const float*)d_in[5];
    const float* W_hh1 = (const float*)d_in[6];
    const float* b_ih1 = (const float*)d_in[7];
    const float* b_hh1 = (const float*)d_in[8];
    float* out = (float*)d_out;

    // Layer 0 input projection -> g_pre
    pre0_kernel<<<BT / P0_ROWS, 128>>>(x, W_ih0, b_ih0, b_hh0);
    // Layer 0 scan: g_pre -> g_h1
    scan_kernel<<<B, 128>>>(0, W_hh0, out);
    // Layer 1 input projection: g_h1 -> g_pre
    proj_kernel<<<PROJ_BLOCKS, 128>>>(W_ih1, b_ih1, b_hh1);
    // Layer 1 scan: g_pre -> out
    scan_kernel<<<B, 128>>>(1, W_hh1, out);
}

// round 14
// speedup vs baseline: 1.9050x; 1.1298x over previous
#include <cuda_runtime.h>
#include <cuda_bf16.h>
#include <cstdint>

#define B   256
#define T   1024
#define H   128
#define I   19
#define BT  (B*T)            // 262144
#define NEL (BT*H)           // 33554432

// Scratch (device globals: allocation-free per harness rules)
__device__ float g_pre[NEL];   // pre-activations (layer0, then layer1)
__device__ float g_h1[NEL];    // layer-0 hidden outputs

typedef unsigned long long u64;

__device__ __forceinline__ u64 fma2(u64 a, u64 b, u64 c) {
    u64 d;
    asm("fma.rn.f32x2 %0, %1, %2, %3;" : "=l"(d) : "l"(a), "l"(b), "l"(c));
    return d;
}
__device__ __forceinline__ u64 add2(u64 a, u64 b) {
    u64 d;
    asm("add.rn.f32x2 %0, %1, %2;" : "=l"(d) : "l"(a), "l"(b));
    return d;
}
__device__ __forceinline__ float red2(u64 a) {
    float x, y;
    asm("mov.b64 {%0, %1}, %2;" : "=f"(x), "=f"(y) : "l"(a));
    return x + y;
}
__device__ __forceinline__ float fast_tanh(float x) {
    float r;
    asm("tanh.approx.f32 %0, %1;" : "=f"(r) : "f"(x));
    return r;
}
__device__ __forceinline__ void cp16(uint32_t daddr, const void* gptr) {
    asm volatile("cp.async.ca.shared.global [%0], [%1], 16;\n"
                 :: "r"(daddr), "l"(gptr));
}

// ---------------------------------------------------------------------------
// Kernel 1: pre0 (proven in round 5)
// ---------------------------------------------------------------------------
#define P0_ROWS 64
#define P0_F4   ((P0_ROWS * I) / 4)   // 304

__global__ void __launch_bounds__(128)
pre0_kernel(const float* __restrict__ x,
            const float* __restrict__ W,
            const float* __restrict__ bi,
            const float* __restrict__ bh) {
    __shared__ __align__(16) float xs[P0_ROWS * I];
    const int j = threadIdx.x;

    float w[I];
#pragma unroll
    for (int f = 0; f < I; f++) w[f] = __ldg(W + j * I + f);
    const float bias = __ldg(bi + j) + __ldg(bh + j);

    const int rbeg = blockIdx.x * P0_ROWS;
    const float4* src = reinterpret_cast<const float4*>(x + (size_t)rbeg * I);
    float4* dst = reinterpret_cast<float4*>(xs);
    dst[j] = src[j];
    dst[j + 128] = src[j + 128];
    if (j < P0_F4 - 256) dst[j + 256] = src[j + 256];
    __syncthreads();

    float* outp = g_pre + (size_t)rbeg * H + j;
#pragma unroll 4
    for (int r = 0; r < P0_ROWS; r += 4) {
        float a0 = bias, a1 = bias, a2 = bias, a3 = bias;
#pragma unroll
        for (int f = 0; f < I; f++) {
            a0 = fmaf(xs[(r + 0) * I + f], w[f], a0);
            a1 = fmaf(xs[(r + 1) * I + f], w[f], a1);
            a2 = fmaf(xs[(r + 2) * I + f], w[f], a2);
            a3 = fmaf(xs[(r + 3) * I + f], w[f], a3);
        }
        outp[(r + 0) * H] = a0;
        outp[(r + 1) * H] = a1;
        outp[(r + 2) * H] = a2;
        outp[(r + 3) * H] = a3;
    }
}

// ---------------------------------------------------------------------------
// Kernel 2: recurrent scan — R5 structure, but 4x-unrolled step loop with
// FOUR statically-named prefetch registers (p0..p3), each consumed exactly
// 4 steps after its LDG issues. No arrays, no dynamic indexing (the R3
// attempt spilled pf[t&3] to local memory, re-exposing DRAM latency; this
// version keeps every prefetch in a named register).
// ---------------------------------------------------------------------------
#define SCAN_STEP(INBUF, OUTBUF, PREG, TT)                                    \
    {                                                                         \
        const ulonglong2* hp = reinterpret_cast<const ulonglong2*>(INBUF);    \
        u64 a0 = 0, a1 = 0, a2 = 0, a3 = 0;                                   \
        _Pragma("unroll")                                                     \
        for (int i = 0; i < 16; i++) {                                        \
            ulonglong2 q0 = hp[2 * i], q1 = hp[2 * i + 1];                    \
            a0 = fma2(wp[4 * i + 0], q0.x, a0);                               \
            a1 = fma2(wp[4 * i + 1], q0.y, a1);                               \
            a2 = fma2(wp[4 * i + 2], q1.x, a2);                               \
            a3 = fma2(wp[4 * i + 3], q1.y, a3);                               \
        }                                                                     \
        float h = fast_tanh(PREG + red2(add2(add2(a0, a2), add2(a1, a3))));   \
        (OUTBUF)[j] = h;                                                      \
        out[base + (TT) * H] = h;                                             \
        int tn = ((TT) + 4 < T) ? ((TT) + 4) : (T - 1);                       \
        PREG = __ldg(pre + base + tn * H);                                    \
        __syncthreads();                                                      \
    }

__global__ void __launch_bounds__(128, 2)
scan_kernel(int layer, const float* __restrict__ Whh, float* __restrict__ dout) {
    __shared__ __align__(16) float hAb[H], hBb[H];
    const int j = threadIdx.x;
    const int b = blockIdx.x;
    const float* __restrict__ pre = g_pre;
    float* __restrict__ out = (layer == 0) ? g_h1 : dout;

    u64 wp[64];
    const u64* wrow = reinterpret_cast<const u64*>(Whh + j * H);
#pragma unroll
    for (int i = 0; i < 64; i++) wp[i] = __ldg(wrow + i);

    hAb[j] = 0.0f;
    const int base = b * (T * H) + j;
    float p0 = __ldg(pre + base);
    float p1 = __ldg(pre + base + H);
    float p2 = __ldg(pre + base + 2 * H);
    float p3 = __ldg(pre + base + 3 * H);
    __syncthreads();

#pragma unroll 1
    for (int t = 0; t < T; t += 4) {
        SCAN_STEP(hAb, hBb, p0, t + 0)
        SCAN_STEP(hBb, hAb, p1, t + 1)
        SCAN_STEP(hAb, hBb, p2, t + 2)
        SCAN_STEP(hBb, hAb, p3, t + 3)
    }
}

// ---------------------------------------------------------------------------
// Kernel 3: layer-1 input projection, 4-stage cp.async pipeline (round 13).
// ---------------------------------------------------------------------------
#define PROJ_BLOCKS 2048
#define PROJ_ROWS   (BT / PROJ_BLOCKS)   // 128 rows per block
#define PTILE       8
#define NTILES      (PROJ_ROWS / PTILE)  // 16
#define NSTAGE      4
#define STAGE_BYTES (PTILE * H * 4)      // 4096

__global__ void __launch_bounds__(128, 2)
proj_kernel(const float* __restrict__ W,
            const float* __restrict__ bi,
            const float* __restrict__ bh) {
    __shared__ __align__(16) float sh[NSTAGE][PTILE * H];
    const int j = threadIdx.x;
    const uint32_t shbase = (uint32_t)__cvta_generic_to_shared(sh);

    u64 wp[64];
    const u64* wrow = reinterpret_cast<const u64*>(W + j * H);
#pragma unroll
    for (int i = 0; i < 64; i++) wp[i] = __ldg(wrow + i);

    const float bias = __ldg(bi + j) + __ldg(bh + j);
    const int rbeg = blockIdx.x * PROJ_ROWS;

#pragma unroll
    for (int s = 0; s < 3; s++) {
        const float4* src = reinterpret_cast<const float4*>(
            g_h1 + (size_t)(rbeg + s * PTILE) * H);
        uint32_t d = shbase + s * STAGE_BYTES + j * 16;
        cp16(d, src + j);
        cp16(d + 2048, src + j + 128);
        asm volatile("cp.async.commit_group;\n");
    }

#pragma unroll 1
    for (int ti = 0; ti < NTILES; ti++) {
        asm volatile("cp.async.wait_group 2;\n");
        __syncthreads();

        if (ti + 3 < NTILES) {
            int s = (ti + 3) & (NSTAGE - 1);
            const float4* src = reinterpret_cast<const float4*>(
                g_h1 + (size_t)(rbeg + (ti + 3) * PTILE) * H);
            uint32_t d = shbase + s * STAGE_BYTES + j * 16;
            cp16(d, src + j);
            cp16(d + 2048, src + j + 128);
            asm volatile("cp.async.commit_group;\n");
        }

        const float* stage = sh[ti & (NSTAGE - 1)];
        float* outp = g_pre + (size_t)(rbeg + ti * PTILE) * H + j;
#pragma unroll
        for (int i = 0; i < PTILE; i++) {
            const ulonglong2* hp = reinterpret_cast<const ulonglong2*>(stage + i * H);
            u64 a0 = 0, a1 = 0, a2 = 0, a3 = 0;
#pragma unroll
            for (int q = 0; q < 16; q++) {
                ulonglong2 x0 = hp[2 * q], x1 = hp[2 * q + 1];
                a0 = fma2(wp[4 * q + 0], x0.x, a0);
                a1 = fma2(wp[4 * q + 1], x0.y, a1);
                a2 = fma2(wp[4 * q + 2], x1.x, a2);
                a3 = fma2(wp[4 * q + 3], x1.y, a3);
            }
            outp[i * H] = bias + red2(add2(add2(a0, a2), add2(a1, a3)));
        }
        __syncthreads();
    }
}

// ---------------------------------------------------------------------------
extern "C" void kernel_launch(void* const* d_in, const int* in_sizes, int n_in,
                              void* d_out, int out_size) {
    const float* x     = (const float*)d_in[0];
    const float* W_ih0 = (const float*)d_in[1];
    const float* W_hh0 = (const float*)d_in[2];
    const float* b_ih0 = (const float*)d_in[3];
    const float* b_hh0 = (const float*)d_in[4];
    const float* W_ih1 = (const float*)d_in[5];
    const float* W_hh1 = (const float*)d_in[6];
    const float* b_ih1 = (const float*)d_in[7];
    const float* b_hh1 = (const float*)d_in[8];
    float* out = (float*)d_out;

    // Layer 0 input projection -> g_pre
    pre0_kernel<<<BT / P0_ROWS, 128>>>(x, W_ih0, b_ih0, b_hh0);
    // Layer 0 scan: g_pre -> g_h1
    scan_kernel<<<B, 128>>>(0, W_hh0, out);
    // Layer 1 input projection: g_h1 -> g_pre
    proj_kernel<<<PROJ_BLOCKS, 128>>>(W_ih1, b_ih1, b_hh1);
    // Layer 1 scan: g_pre -> out
    scan_kernel<<<B, 128>>>(1, W_hh1, out);
}

// round 15
// speedup vs baseline: 2.0008x; 1.0503x over previous
#include <cuda_runtime.h>
#include <cuda_bf16.h>
#include <cstdint>

#define B   256
#define T   1024
#define H   128
#define I   19
#define BT  (B*T)            // 262144
#define NEL (BT*H)           // 33554432

// Scratch (device globals: allocation-free per harness rules)
__device__ float g_pre[NEL];   // pre-activations (layer0, then layer1)
__device__ float g_h1[NEL];    // layer-0 hidden outputs

typedef unsigned long long u64;

__device__ __forceinline__ u64 fma2(u64 a, u64 b, u64 c) {
    u64 d;
    asm("fma.rn.f32x2 %0, %1, %2, %3;" : "=l"(d) : "l"(a), "l"(b), "l"(c));
    return d;
}
__device__ __forceinline__ u64 add2(u64 a, u64 b) {
    u64 d;
    asm("add.rn.f32x2 %0, %1, %2;" : "=l"(d) : "l"(a), "l"(b));
    return d;
}
__device__ __forceinline__ float red2(u64 a) {
    float x, y;
    asm("mov.b64 {%0, %1}, %2;" : "=f"(x), "=f"(y) : "l"(a));
    return x + y;
}
__device__ __forceinline__ float fast_tanh(float x) {
    float r;
    asm("tanh.approx.f32 %0, %1;" : "=f"(r) : "f"(x));
    return r;
}
__device__ __forceinline__ void cp16(uint32_t daddr, const void* gptr) {
    asm volatile("cp.async.ca.shared.global [%0], [%1], 16;\n"
                 :: "r"(daddr), "l"(gptr));
}

// ---------------------------------------------------------------------------
// Kernel 1: pre0 (proven in round 5)
// ---------------------------------------------------------------------------
#define P0_ROWS 64
#define P0_F4   ((P0_ROWS * I) / 4)   // 304

__global__ void __launch_bounds__(128)
pre0_kernel(const float* __restrict__ x,
            const float* __restrict__ W,
            const float* __restrict__ bi,
            const float* __restrict__ bh) {
    __shared__ __align__(16) float xs[P0_ROWS * I];
    const int j = threadIdx.x;

    float w[I];
#pragma unroll
    for (int f = 0; f < I; f++) w[f] = __ldg(W + j * I + f);
    const float bias = __ldg(bi + j) + __ldg(bh + j);

    const int rbeg = blockIdx.x * P0_ROWS;
    const float4* src = reinterpret_cast<const float4*>(x + (size_t)rbeg * I);
    float4* dst = reinterpret_cast<float4*>(xs);
    dst[j] = src[j];
    dst[j + 128] = src[j + 128];
    if (j < P0_F4 - 256) dst[j + 256] = src[j + 256];
    __syncthreads();

    float* outp = g_pre + (size_t)rbeg * H + j;
#pragma unroll 4
    for (int r = 0; r < P0_ROWS; r += 4) {
        float a0 = bias, a1 = bias, a2 = bias, a3 = bias;
#pragma unroll
        for (int f = 0; f < I; f++) {
            a0 = fmaf(xs[(r + 0) * I + f], w[f], a0);
            a1 = fmaf(xs[(r + 1) * I + f], w[f], a1);
            a2 = fmaf(xs[(r + 2) * I + f], w[f], a2);
            a3 = fmaf(xs[(r + 3) * I + f], w[f], a3);
        }
        outp[(r + 0) * H] = a0;
        outp[(r + 1) * H] = a1;
        outp[(r + 2) * H] = a2;
        outp[(r + 3) * H] = a3;
    }
}

// ---------------------------------------------------------------------------
// Kernel 2: recurrent scan — R14 structure deepened to an 8-deep prefetch
// pipeline: EIGHT statically-named prefetch registers (p0..p7), each
// consumed exactly 8 steps after its LDG issues (no arrays -> no local-mem
// spill). STG of h issued AFTER the STS so the barrier-drained shared write
// is not delayed by the global store. 8x-unrolled step loop (T % 8 == 0).
// ---------------------------------------------------------------------------
#define SCAN_STEP(INBUF, OUTBUF, PREG, TT)                                    \
    {                                                                         \
        const ulonglong2* hp = reinterpret_cast<const ulonglong2*>(INBUF);    \
        u64 a0 = 0, a1 = 0, a2 = 0, a3 = 0;                                   \
        _Pragma("unroll")                                                     \
        for (int i = 0; i < 16; i++) {                                        \
            ulonglong2 q0 = hp[2 * i], q1 = hp[2 * i + 1];                    \
            a0 = fma2(wp[4 * i + 0], q0.x, a0);                               \
            a1 = fma2(wp[4 * i + 1], q0.y, a1);                               \
            a2 = fma2(wp[4 * i + 2], q1.x, a2);                               \
            a3 = fma2(wp[4 * i + 3], q1.y, a3);                               \
        }                                                                     \
        float h = fast_tanh(PREG + red2(add2(add2(a0, a2), add2(a1, a3))));   \
        (OUTBUF)[j] = h;                                                      \
        int tn = ((TT) + 8 < T) ? ((TT) + 8) : (T - 1);                       \
        PREG = __ldg(pre + base + tn * H);                                    \
        out[base + (TT) * H] = h;                                             \
        __syncthreads();                                                      \
    }

__global__ void __launch_bounds__(128, 2)
scan_kernel(int layer, const float* __restrict__ Whh, float* __restrict__ dout) {
    __shared__ __align__(16) float hAb[H], hBb[H];
    const int j = threadIdx.x;
    const int b = blockIdx.x;
    const float* __restrict__ pre = g_pre;
    float* __restrict__ out = (layer == 0) ? g_h1 : dout;

    u64 wp[64];
    const u64* wrow = reinterpret_cast<const u64*>(Whh + j * H);
#pragma unroll
    for (int i = 0; i < 64; i++) wp[i] = __ldg(wrow + i);

    hAb[j] = 0.0f;
    const int base = b * (T * H) + j;
    float p0 = __ldg(pre + base);
    float p1 = __ldg(pre + base + 1 * H);
    float p2 = __ldg(pre + base + 2 * H);
    float p3 = __ldg(pre + base + 3 * H);
    float p4 = __ldg(pre + base + 4 * H);
    float p5 = __ldg(pre + base + 5 * H);
    float p6 = __ldg(pre + base + 6 * H);
    float p7 = __ldg(pre + base + 7 * H);
    __syncthreads();

#pragma unroll 1
    for (int t = 0; t < T; t += 8) {
        SCAN_STEP(hAb, hBb, p0, t + 0)
        SCAN_STEP(hBb, hAb, p1, t + 1)
        SCAN_STEP(hAb, hBb, p2, t + 2)
        SCAN_STEP(hBb, hAb, p3, t + 3)
        SCAN_STEP(hAb, hBb, p4, t + 4)
        SCAN_STEP(hBb, hAb, p5, t + 5)
        SCAN_STEP(hAb, hBb, p6, t + 6)
        SCAN_STEP(hBb, hAb, p7, t + 7)
    }
}

// ---------------------------------------------------------------------------
// Kernel 3: layer-1 input projection, 4-stage cp.async pipeline (round 13).
// ---------------------------------------------------------------------------
#define PROJ_BLOCKS 2048
#define PROJ_ROWS   (BT / PROJ_BLOCKS)   // 128 rows per block
#define PTILE       8
#define NTILES      (PROJ_ROWS / PTILE)  // 16
#define NSTAGE      4
#define STAGE_BYTES (PTILE * H * 4)      // 4096

__global__ void __launch_bounds__(128, 2)
proj_kernel(const float* __restrict__ W,
            const float* __restrict__ bi,
            const float* __restrict__ bh) {
    __shared__ __align__(16) float sh[NSTAGE][PTILE * H];
    const int j = threadIdx.x;
    const uint32_t shbase = (uint32_t)__cvta_generic_to_shared(sh);

    u64 wp[64];
    const u64* wrow = reinterpret_cast<const u64*>(W + j * H);
#pragma unroll
    for (int i = 0; i < 64; i++) wp[i] = __ldg(wrow + i);

    const float bias = __ldg(bi + j) + __ldg(bh + j);
    const int rbeg = blockIdx.x * PROJ_ROWS;

#pragma unroll
    for (int s = 0; s < 3; s++) {
        const float4* src = reinterpret_cast<const float4*>(
            g_h1 + (size_t)(rbeg + s * PTILE) * H);
        uint32_t d = shbase + s * STAGE_BYTES + j * 16;
        cp16(d, src + j);
        cp16(d + 2048, src + j + 128);
        asm volatile("cp.async.commit_group;\n");
    }

#pragma unroll 1
    for (int ti = 0; ti < NTILES; ti++) {
        asm volatile("cp.async.wait_group 2;\n");
        __syncthreads();

        if (ti + 3 < NTILES) {
            int s = (ti + 3) & (NSTAGE - 1);
            const float4* src = reinterpret_cast<const float4*>(
                g_h1 + (size_t)(rbeg + (ti + 3) * PTILE) * H);
            uint32_t d = shbase + s * STAGE_BYTES + j * 16;
            cp16(d, src + j);
            cp16(d + 2048, src + j + 128);
            asm volatile("cp.async.commit_group;\n");
        }

        const float* stage = sh[ti & (NSTAGE - 1)];
        float* outp = g_pre + (size_t)(rbeg + ti * PTILE) * H + j;
#pragma unroll
        for (int i = 0; i < PTILE; i++) {
            const ulonglong2* hp = reinterpret_cast<const ulonglong2*>(stage + i * H);
            u64 a0 = 0, a1 = 0, a2 = 0, a3 = 0;
#pragma unroll
            for (int q = 0; q < 16; q++) {
                ulonglong2 x0 = hp[2 * q], x1 = hp[2 * q + 1];
                a0 = fma2(wp[4 * q + 0], x0.x, a0);
                a1 = fma2(wp[4 * q + 1], x0.y, a1);
                a2 = fma2(wp[4 * q + 2], x1.x, a2);
                a3 = fma2(wp[4 * q + 3], x1.y, a3);
            }
            outp[i * H] = bias + red2(add2(add2(a0, a2), add2(a1, a3)));
        }
        __syncthreads();
    }
}

// ---------------------------------------------------------------------------
extern "C" void kernel_launch(void* const* d_in, const int* in_sizes, int n_in,
                              void* d_out, int out_size) {
    const float* x     = (const float*)d_in[0];
    const float* W_ih0 = (const float*)d_in[1];
    const float* W_hh0 = (const float*)d_in[2];
    const float* b_ih0 = (const float*)d_in[3];
    const float* b_hh0 = (const float*)d_in[4];
    const float* W_ih1 = (const float*)d_in[5];
    const float* W_hh1 = (const float*)d_in[6];
    const float* b_ih1 = (const float*)d_in[7];
    const float* b_hh1 = (const float*)d_in[8];
    float* out = (float*)d_out;

    // Layer 0 input projection -> g_pre
    pre0_kernel<<<BT / P0_ROWS, 128>>>(x, W_ih0, b_ih0, b_hh0);
    // Layer 0 scan: g_pre -> g_h1
    scan_kernel<<<B, 128>>>(0, W_hh0, out);
    // Layer 1 input projection: g_h1 -> g_pre
    proj_kernel<<<PROJ_BLOCKS, 128>>>(W_ih1, b_ih1, b_hh1);
    // Layer 1 scan: g_pre -> out
    scan_kernel<<<B, 128>>>(1, W_hh1, out);
}

// round 16
// speedup vs baseline: 2.0443x; 1.0218x over previous
#include <cuda_runtime.h>
#include <cuda_bf16.h>
#include <cstdint>

#define B   256
#define T   1024
#define H   128
#define I   19
#define BT  (B*T)            // 262144
#define NEL (BT*H)           // 33554432

// Scratch (device globals: allocation-free per harness rules)
__device__ float g_pre[NEL];   // pre-activations (layer0, then layer1)
__device__ float g_h1[NEL];    // layer-0 hidden outputs

typedef unsigned long long u64;

__device__ __forceinline__ u64 fma2(u64 a, u64 b, u64 c) {
    u64 d;
    asm("fma.rn.f32x2 %0, %1, %2, %3;" : "=l"(d) : "l"(a), "l"(b), "l"(c));
    return d;
}
__device__ __forceinline__ u64 add2(u64 a, u64 b) {
    u64 d;
    asm("add.rn.f32x2 %0, %1, %2;" : "=l"(d) : "l"(a), "l"(b));
    return d;
}
__device__ __forceinline__ float red2(u64 a) {
    float x, y;
    asm("mov.b64 {%0, %1}, %2;" : "=f"(x), "=f"(y) : "l"(a));
    return x + y;
}
__device__ __forceinline__ float fast_tanh(float x) {
    float r;
    asm("tanh.approx.f32 %0, %1;" : "=f"(r) : "f"(x));
    return r;
}
__device__ __forceinline__ void cp16(uint32_t daddr, const void* gptr) {
    asm volatile("cp.async.ca.shared.global [%0], [%1], 16;\n"
                 :: "r"(daddr), "l"(gptr));
}

// ---------------------------------------------------------------------------
// Kernel 1: pre0 (proven in round 5)
// ---------------------------------------------------------------------------
#define P0_ROWS 64
#define P0_F4   ((P0_ROWS * I) / 4)   // 304

__global__ void __launch_bounds__(128)
pre0_kernel(const float* __restrict__ x,
            const float* __restrict__ W,
            const float* __restrict__ bi,
            const float* __restrict__ bh) {
    __shared__ __align__(16) float xs[P0_ROWS * I];
    const int j = threadIdx.x;

    float w[I];
#pragma unroll
    for (int f = 0; f < I; f++) w[f] = __ldg(W + j * I + f);
    const float bias = __ldg(bi + j) + __ldg(bh + j);

    const int rbeg = blockIdx.x * P0_ROWS;
    const float4* src = reinterpret_cast<const float4*>(x + (size_t)rbeg * I);
    float4* dst = reinterpret_cast<float4*>(xs);
    dst[j] = src[j];
    dst[j + 128] = src[j + 128];
    if (j < P0_F4 - 256) dst[j + 256] = src[j + 256];
    __syncthreads();

    float* outp = g_pre + (size_t)rbeg * H + j;
#pragma unroll 4
    for (int r = 0; r < P0_ROWS; r += 4) {
        float a0 = bias, a1 = bias, a2 = bias, a3 = bias;
#pragma unroll
        for (int f = 0; f < I; f++) {
            a0 = fmaf(xs[(r + 0) * I + f], w[f], a0);
            a1 = fmaf(xs[(r + 1) * I + f], w[f], a1);
            a2 = fmaf(xs[(r + 2) * I + f], w[f], a2);
            a3 = fmaf(xs[(r + 3) * I + f], w[f], a3);
        }
        outp[(r + 0) * H] = a0;
        outp[(r + 1) * H] = a1;
        outp[(r + 2) * H] = a2;
        outp[(r + 3) * H] = a3;
    }
}

// ---------------------------------------------------------------------------
// Kernel 2: recurrent scan — 16-deep named-register prefetch pipeline
// (p0..pF, each consumed exactly 16 steps after its LDG issues; no arrays,
// no local-mem spill). 16x-unrolled step loop (T % 16 == 0). STS before
// STG so the barrier-drained shared write is not delayed.
// ---------------------------------------------------------------------------
#define SCAN_STEP(INBUF, OUTBUF, PREG, TT)                                    \
    {                                                                         \
        const ulonglong2* hp = reinterpret_cast<const ulonglong2*>(INBUF);    \
        u64 a0 = 0, a1 = 0, a2 = 0, a3 = 0;                                   \
        _Pragma("unroll")                                                     \
        for (int i = 0; i < 16; i++) {                                        \
            ulonglong2 q0 = hp[2 * i], q1 = hp[2 * i + 1];                    \
            a0 = fma2(wp[4 * i + 0], q0.x, a0);                               \
            a1 = fma2(wp[4 * i + 1], q0.y, a1);                               \
            a2 = fma2(wp[4 * i + 2], q1.x, a2);                               \
            a3 = fma2(wp[4 * i + 3], q1.y, a3);                               \
        }                                                                     \
        float h = fast_tanh(PREG + red2(add2(add2(a0, a2), add2(a1, a3))));   \
        (OUTBUF)[j] = h;                                                      \
        int tn = ((TT) + 16 < T) ? ((TT) + 16) : (T - 1);                     \
        PREG = __ldg(pre + base + tn * H);                                    \
        out[base + (TT) * H] = h;                                             \
        __syncthreads();                                                      \
    }

__global__ void __launch_bounds__(128, 2)
scan_kernel(int layer, const float* __restrict__ Whh, float* __restrict__ dout) {
    __shared__ __align__(16) float hAb[H], hBb[H];
    const int j = threadIdx.x;
    const int b = blockIdx.x;
    const float* __restrict__ pre = g_pre;
    float* __restrict__ out = (layer == 0) ? g_h1 : dout;

    u64 wp[64];
    const u64* wrow = reinterpret_cast<const u64*>(Whh + j * H);
#pragma unroll
    for (int i = 0; i < 64; i++) wp[i] = __ldg(wrow + i);

    hAb[j] = 0.0f;
    const int base = b * (T * H) + j;
    float p0 = __ldg(pre + base);
    float p1 = __ldg(pre + base + 1 * H);
    float p2 = __ldg(pre + base + 2 * H);
    float p3 = __ldg(pre + base + 3 * H);
    float p4 = __ldg(pre + base + 4 * H);
    float p5 = __ldg(pre + base + 5 * H);
    float p6 = __ldg(pre + base + 6 * H);
    float p7 = __ldg(pre + base + 7 * H);
    float p8 = __ldg(pre + base + 8 * H);
    float p9 = __ldg(pre + base + 9 * H);
    float pa = __ldg(pre + base + 10 * H);
    float pb = __ldg(pre + base + 11 * H);
    float pc = __ldg(pre + base + 12 * H);
    float pd = __ldg(pre + base + 13 * H);
    float pe = __ldg(pre + base + 14 * H);
    float pf = __ldg(pre + base + 15 * H);
    __syncthreads();

#pragma unroll 1
    for (int t = 0; t < T; t += 16) {
        SCAN_STEP(hAb, hBb, p0, t + 0)
        SCAN_STEP(hBb, hAb, p1, t + 1)
        SCAN_STEP(hAb, hBb, p2, t + 2)
        SCAN_STEP(hBb, hAb, p3, t + 3)
        SCAN_STEP(hAb, hBb, p4, t + 4)
        SCAN_STEP(hBb, hAb, p5, t + 5)
        SCAN_STEP(hAb, hBb, p6, t + 6)
        SCAN_STEP(hBb, hAb, p7, t + 7)
        SCAN_STEP(hAb, hBb, p8, t + 8)
        SCAN_STEP(hBb, hAb, p9, t + 9)
        SCAN_STEP(hAb, hBb, pa, t + 10)
        SCAN_STEP(hBb, hAb, pb, t + 11)
        SCAN_STEP(hAb, hBb, pc, t + 12)
        SCAN_STEP(hBb, hAb, pd, t + 13)
        SCAN_STEP(hAb, hBb, pe, t + 14)
        SCAN_STEP(hBb, hAb, pf, t + 15)
    }
}

// ---------------------------------------------------------------------------
// Kernel 3: layer-1 input projection, 4-stage cp.async pipeline.
// CHANGE: __launch_bounds__(128, 3) — 3 CTAs/SM (smem 3x16KB, regs <=170)
// to fill latency holes with CTA-level parallelism.
// ---------------------------------------------------------------------------
#define PROJ_BLOCKS 2048
#define PROJ_ROWS   (BT / PROJ_BLOCKS)   // 128 rows per block
#define PTILE       8
#define NTILES      (PROJ_ROWS / PTILE)  // 16
#define NSTAGE      4
#define STAGE_BYTES (PTILE * H * 4)      // 4096

__global__ void __launch_bounds__(128, 3)
proj_kernel(const float* __restrict__ W,
            const float* __restrict__ bi,
            const float* __restrict__ bh) {
    __shared__ __align__(16) float sh[NSTAGE][PTILE * H];
    const int j = threadIdx.x;
    const uint32_t shbase = (uint32_t)__cvta_generic_to_shared(sh);

    u64 wp[64];
    const u64* wrow = reinterpret_cast<const u64*>(W + j * H);
#pragma unroll
    for (int i = 0; i < 64; i++) wp[i] = __ldg(wrow + i);

    const float bias = __ldg(bi + j) + __ldg(bh + j);
    const int rbeg = blockIdx.x * PROJ_ROWS;

#pragma unroll
    for (int s = 0; s < 3; s++) {
        const float4* src = reinterpret_cast<const float4*>(
            g_h1 + (size_t)(rbeg + s * PTILE) * H);
        uint32_t d = shbase + s * STAGE_BYTES + j * 16;
        cp16(d, src + j);
        cp16(d + 2048, src + j + 128);
        asm volatile("cp.async.commit_group;\n");
    }

#pragma unroll 1
    for (int ti = 0; ti < NTILES; ti++) {
        asm volatile("cp.async.wait_group 2;\n");
        __syncthreads();

        if (ti + 3 < NTILES) {
            int s = (ti + 3) & (NSTAGE - 1);
            const float4* src = reinterpret_cast<const float4*>(
                g_h1 + (size_t)(rbeg + (ti + 3) * PTILE) * H);
            uint32_t d = shbase + s * STAGE_BYTES + j * 16;
            cp16(d, src + j);
            cp16(d + 2048, src + j + 128);
            asm volatile("cp.async.commit_group;\n");
        }

        const float* stage = sh[ti & (NSTAGE - 1)];
        float* outp = g_pre + (size_t)(rbeg + ti * PTILE) * H + j;
#pragma unroll
        for (int i = 0; i < PTILE; i++) {
            const ulonglong2* hp = reinterpret_cast<const ulonglong2*>(stage + i * H);
            u64 a0 = 0, a1 = 0, a2 = 0, a3 = 0;
#pragma unroll
            for (int q = 0; q < 16; q++) {
                ulonglong2 x0 = hp[2 * q], x1 = hp[2 * q + 1];
                a0 = fma2(wp[4 * q + 0], x0.x, a0);
                a1 = fma2(wp[4 * q + 1], x0.y, a1);
                a2 = fma2(wp[4 * q + 2], x1.x, a2);
                a3 = fma2(wp[4 * q + 3], x1.y, a3);
            }
            outp[i * H] = bias + red2(add2(add2(a0, a2), add2(a1, a3)));
        }
        __syncthreads();
    }
}

// ---------------------------------------------------------------------------
extern "C" void kernel_launch(void* const* d_in, const int* in_sizes, int n_in,
                              void* d_out, int out_size) {
    const float* x     = (const float*)d_in[0];
    const float* W_ih0 = (const float*)d_in[1];
    const float* W_hh0 = (const float*)d_in[2];
    const float* b_ih0 = (const float*)d_in[3];
    const float* b_hh0 = (const float*)d_in[4];
    const float* W_ih1 = (const float*)d_in[5];
    const float* W_hh1 = (const float*)d_in[6];
    const float* b_ih1 = (const float*)d_in[7];
    const float* b_hh1 = (const float*)d_in[8];
    float* out = (float*)d_out;

    // Layer 0 input projection -> g_pre
    pre0_kernel<<<BT / P0_ROWS, 128>>>(x, W_ih0, b_ih0, b_hh0);
    // Layer 0 scan: g_pre -> g_h1
    scan_kernel<<<B, 128>>>(0, W_hh0, out);
    // Layer 1 input projection: g_h1 -> g_pre
    proj_kernel<<<PROJ_BLOCKS, 128>>>(W_ih1, b_ih1, b_hh1);
    // Layer 1 scan: g_pre -> out
    scan_kernel<<<B, 128>>>(1, W_hh1, out);
}